// round 3
// baseline (speedup 1.0000x reference)
#include <cuda_runtime.h>
#include <math.h>

#define KE_KCAL 332.0636f

// ---------------- scratch (no allocations allowed) ----------------
struct Consts {
    float c[4], ex[4];
    float csum_inv, dinv;
};
__device__ Consts g_c;
__device__ float    g_zpow[128];        // z^z_exp lookup
__device__ int      g_prefix[1026];     // prefix of num_atoms (M<=1024)
__device__ float4   g_atoms[262144];    // packed per-atom: x,y,z, (z | mol<<8)
__device__ float    g_acc[1024 * 32];   // padded per-molecule accumulators
__device__ unsigned g_done;             // block-completion counter

// ---------------- setup: consts + zpow + prefix scan, one launch ----------------
__global__ void k_setup(const float* __restrict__ d_inv,
                        const float* __restrict__ ze_inv,
                        const float* __restrict__ c_inv,
                        const float* __restrict__ ex_inv,
                        const int*   __restrict__ na, int M) {
    __shared__ float s_zexp;
    __shared__ int s[1024];
    int t = threadIdx.x;
    if (t == 0) {
        g_done = 0;
        float d  = log1pf(expf(d_inv[0]));
        float ze = log1pf(expf(ze_inv[0]));
        s_zexp = ze;
        float csum = 0.f;
        #pragma unroll
        for (int k = 0; k < 4; k++) {
            float ck = log1pf(expf(c_inv[k]));
            float ek = log1pf(expf(ex_inv[k]));
            g_c.c[k] = ck; g_c.ex[k] = ek;
            csum += ck;
        }
        g_c.csum_inv = 1.f / csum;
        g_c.dinv     = 1.f / d;
    }
    int v = (t < M) ? na[t] : 0;
    s[t] = v;
    __syncthreads();
    float ze = s_zexp;
    if (t < 128) g_zpow[t] = (t == 0) ? 0.f : powf((float)t, ze);
    for (int o = 1; o < 1024; o <<= 1) {
        int x = (t >= o) ? s[t - o] : 0;
        __syncthreads();
        s[t] += x;
        __syncthreads();
    }
    if (t == 0) { g_prefix[0] = 0; g_prefix[M + 1] = 0x7fffffff; }
    if (t < M) g_prefix[t + 1] = s[t];
}

// ---------------- atom packing (4 atoms/thread) + acc zeroing ----------------
__global__ void __launch_bounds__(256)
k_atoms(const float* __restrict__ xyz,
        const int*   __restrict__ z,
        int N, int M) {
    __shared__ int sp[1026];
    int t = threadIdx.x;
    for (int k = t; k <= M + 1; k += blockDim.x) sp[k] = g_prefix[k];
    __syncthreads();

    int gtid = blockIdx.x * blockDim.x + t;

    if (gtid < 2048) {
        float4 zv = make_float4(0.f, 0.f, 0.f, 0.f);
        #pragma unroll
        for (int k = 0; k < 4; k++)
            ((float4*)g_acc)[gtid + k * 2048] = zv;
    }

    int base = gtid * 4;
    if (base >= N) return;

    int lo = 0, hi = M;
    while (hi - lo > 1) {
        int mid = (lo + hi) >> 1;
        if (sp[mid] <= base) lo = mid; else hi = mid;
    }

    if (base + 4 <= N) {
        const float4* x4 = (const float4*)(xyz + base * 3);
        float4 p0 = x4[0], p1 = x4[1], p2 = x4[2];
        int4 zz = *(const int4*)(z + base);
        float xs[4] = {p0.x, p0.w, p1.z, p2.y};
        float ys[4] = {p0.y, p1.x, p1.w, p2.z};
        float zs[4] = {p0.z, p1.y, p2.x, p2.w};
        int   zi[4] = {zz.x, zz.y, zz.z, zz.w};
        #pragma unroll
        for (int k = 0; k < 4; k++) {
            int a = base + k;
            while (sp[lo + 1] <= a) lo++;
            float4 v;
            v.x = xs[k]; v.y = ys[k]; v.z = zs[k];
            v.w = __int_as_float((zi[k] & 255) | (lo << 8));
            g_atoms[a] = v;
        }
    } else {
        for (int a = base; a < N; a++) {
            while (sp[lo + 1] <= a) lo++;
            float4 v;
            v.x = xyz[3 * a]; v.y = xyz[3 * a + 1]; v.z = xyz[3 * a + 2];
            v.w = __int_as_float((z[a] & 255) | (lo << 8));
            g_atoms[a] = v;
        }
    }
}

// ---------------- main edge kernel: 8 edges/thread + fused final reduce ----------------
__global__ void __launch_bounds__(256)
k_edges(const int4* __restrict__ nb4, const float4* __restrict__ off4,
        const int2* __restrict__ nb, const float* __restrict__ off,
        int E, float* __restrict__ out, int M) {
    __shared__ float s_zpow[128];
    __shared__ int s_last;
    if (threadIdx.x < 128) s_zpow[threadIdx.x] = g_zpow[threadIdx.x];
    __syncthreads();

    const float c0 = g_c.c[0],  c1 = g_c.c[1],  c2 = g_c.c[2],  c3 = g_c.c[3];
    const float e0 = g_c.ex[0], e1 = g_c.ex[1], e2 = g_c.ex[2], e3 = g_c.ex[3];
    const float csi  = g_c.csum_inv;
    const float dinv = g_c.dinv;
    const int slot = threadIdx.x & 31;

    auto body = [&](int i, int j, float ox, float oy, float oz) {
        if (j <= i) return;
        float4 ai = g_atoms[i];
        float4 aj = g_atoms[j];
        float dx = ai.x - aj.x - ox;
        float dy = ai.y - aj.y - oy;
        float dz = ai.z - aj.z - oz;
        float d2 = fmaf(dx, dx, fmaf(dy, dy, dz * dz)) + 3e-15f;
        if (d2 >= 25.f) return;
        float rinv = rsqrtf(d2);
        float r    = d2 * rinv;
        int wi = __float_as_int(ai.w);
        int wj = __float_as_int(aj.w);
        float zp = s_zpow[wi & 255] + s_zpow[wj & 255];
        float tt = -r * zp * dinv;
        float phi = fmaf(c0, __expf(e0 * tt),
                    fmaf(c1, __expf(e1 * tt),
                    fmaf(c2, __expf(e2 * tt),
                         c3 * __expf(e3 * tt))));
        float fcut = __expf(__fdividef(-d2, 25.f - d2));
        float zi = (float)(wi & 255);
        float zj = (float)(wj & 255);
        float pair = KE_KCAL * zi * zj * rinv * phi * csi * fcut;
        atomicAdd(&g_acc[((wi >> 8) << 5) + slot], pair);
    };

    int t = blockIdx.x * blockDim.x + threadIdx.x;
    int G = E >> 3;            // groups of 8 edges
    if (t < G) {
        // front-batched loads: 4x int4 + 6x float4 (MLP = 10)
        int4 n0 = nb4[4 * t], n1 = nb4[4 * t + 1], n2 = nb4[4 * t + 2], n3 = nb4[4 * t + 3];
        float4 o0 = off4[6 * t],     o1 = off4[6 * t + 1], o2 = off4[6 * t + 2];
        float4 o3 = off4[6 * t + 3], o4 = off4[6 * t + 4], o5 = off4[6 * t + 5];
        body(n0.x, n0.y, o0.x, o0.y, o0.z);
        body(n0.z, n0.w, o0.w, o1.x, o1.y);
        body(n1.x, n1.y, o1.z, o1.w, o2.x);
        body(n1.z, n1.w, o2.y, o2.z, o2.w);
        body(n2.x, n2.y, o3.x, o3.y, o3.z);
        body(n2.z, n2.w, o3.w, o4.x, o4.y);
        body(n3.x, n3.y, o4.z, o4.w, o5.x);
        body(n3.z, n3.w, o5.y, o5.z, o5.w);
    }
    if (t == 0) {              // tail edges
        for (int e = G * 8; e < E; e++) {
            int2 p = nb[e];
            body(p.x, p.y, off[3 * e], off[3 * e + 1], off[3 * e + 2]);
        }
    }

    // ---- fused final reduce: last block to finish sums g_acc -> out ----
    __threadfence();
    __syncthreads();
    if (threadIdx.x == 0)
        s_last = (atomicAdd(&g_done, 1u) == gridDim.x - 1);
    __syncthreads();
    if (s_last) {
        for (int m = threadIdx.x; m < M; m += blockDim.x) {
            const float4* a4 = (const float4*)&g_acc[m << 5];
            float s = 0.f;
            #pragma unroll
            for (int k = 0; k < 8; k++) {
                float4 v = __ldcg(&a4[k]);
                s += v.x + v.y + v.z + v.w;
            }
            out[m] = s;
        }
    }
}

// ---------------- launch ----------------
extern "C" void kernel_launch(void* const* d_in, const int* in_sizes, int n_in,
                              void* d_out, int out_size) {
    const float* xyz    = (const float*)d_in[0];
    const int*   z      = (const int*)  d_in[1];
    const int*   nbrs   = (const int*)  d_in[2];
    const int*   natoms = (const int*)  d_in[3];
    const float* off    = (const float*)d_in[4];
    const float* d_inv  = (const float*)d_in[5];
    const float* ze_inv = (const float*)d_in[6];
    const float* c_inv  = (const float*)d_in[7];
    const float* ex_inv = (const float*)d_in[8];

    int N = in_sizes[1];
    int E = in_sizes[2] / 2;
    int M = in_sizes[3];
    float* out = (float*)d_out;

    k_setup<<<1, 1024>>>(d_inv, ze_inv, c_inv, ex_inv, natoms, M);
    int atomThreads = (N + 3) / 4;
    k_atoms<<<(atomThreads + 255) / 256, 256>>>(xyz, z, N, M);
    int G = E / 8;
    k_edges<<<(G + 255) / 256, 256>>>((const int4*)nbrs, (const float4*)off,
                                      (const int2*)nbrs, off, E, out, M);
}

// round 4
// speedup vs baseline: 1.3160x; 1.3160x over previous
#include <cuda_runtime.h>
#include <math.h>

#define KE_KCAL 332.0636f

// ---------------- scratch (no allocations allowed) ----------------
__device__ float4 g_atoms[262144];    // packed per-atom: x,y,z, (z | mol<<8)
__device__ float  g_acc[1024 * 32];   // padded per-molecule accumulators

// ---------------- atom packing: per-block redundant scan + pack + acc zero ----
__global__ void __launch_bounds__(256)
k_atoms(const float* __restrict__ xyz,
        const int*   __restrict__ z,
        const int*   __restrict__ na,
        int N, int M) {
    __shared__ int sp[1026];          // sp[m] = prefix (exclusive), sp[M+1] sentinel
    __shared__ int s_wsum[8];
    int t = threadIdx.x;
    int lane = t & 31, warp = t >> 5;

    // ---- warp-shuffle scan of num_atoms (4 elems/thread, 256 threads -> 1024) ----
    int v0 = (4 * t + 0 < M) ? __ldg(&na[4 * t + 0]) : 0;
    int v1 = (4 * t + 1 < M) ? __ldg(&na[4 * t + 1]) : 0;
    int v2 = (4 * t + 2 < M) ? __ldg(&na[4 * t + 2]) : 0;
    int v3 = (4 * t + 3 < M) ? __ldg(&na[4 * t + 3]) : 0;
    int mysum = v0 + v1 + v2 + v3;
    int sc = mysum;
    #pragma unroll
    for (int o = 1; o < 32; o <<= 1) {
        int x = __shfl_up_sync(0xffffffffu, sc, o);
        if (lane >= o) sc += x;
    }
    if (lane == 31) s_wsum[warp] = sc;
    __syncthreads();
    if (warp == 0 && lane < 8) {
        int ws = s_wsum[lane];
        #pragma unroll
        for (int o = 1; o < 8; o <<= 1) {
            int x = __shfl_up_sync(0xffu, ws, o);
            if (lane >= o) ws += x;
        }
        s_wsum[lane] = ws;
    }
    __syncthreads();
    int base_excl = sc - mysum + (warp > 0 ? s_wsum[warp - 1] : 0);
    // write exclusive prefix at indices 4t+0..3 (sp[m] = atoms before molecule m)
    sp[4 * t + 0] = base_excl;
    sp[4 * t + 1] = base_excl + v0;
    sp[4 * t + 2] = base_excl + v0 + v1;
    sp[4 * t + 3] = base_excl + v0 + v1 + v2;
    if (t == 0) { sp[1024] = 0x7fffffff; sp[1025] = 0x7fffffff; }
    __syncthreads();
    if (t == 0 && M < 1024) sp[M] = base_excl; // unused region; sentinel below covers
    // note: sp[m] for m>=M equals total count; searches never exceed M anyway
    __syncthreads();

    int gtid = blockIdx.x * blockDim.x + t;

    // zero accumulators (first 2048 threads, float4 stores)
    if (gtid < 2048) {
        float4 zv = make_float4(0.f, 0.f, 0.f, 0.f);
        #pragma unroll
        for (int k = 0; k < 4; k++)
            ((float4*)g_acc)[gtid + k * 2048] = zv;
    }

    int base = gtid * 4;
    if (base >= N) return;

    // binary search: largest m with sp[m] <= base (exclusive prefix)
    int lo = 0, hi = M;
    while (hi - lo > 1) {
        int mid = (lo + hi) >> 1;
        if (sp[mid] <= base) lo = mid; else hi = mid;
    }

    if (base + 4 <= N) {
        const float4* x4 = (const float4*)(xyz + base * 3);
        float4 p0 = x4[0], p1 = x4[1], p2 = x4[2];
        int4 zz = *(const int4*)(z + base);
        float xs[4] = {p0.x, p0.w, p1.z, p2.y};
        float ys[4] = {p0.y, p1.x, p1.w, p2.z};
        float zs[4] = {p0.z, p1.y, p2.x, p2.w};
        int   zi[4] = {zz.x, zz.y, zz.z, zz.w};
        #pragma unroll
        for (int k = 0; k < 4; k++) {
            int a = base + k;
            while (lo + 1 < M && sp[lo + 1] <= a) lo++;
            float4 v;
            v.x = xs[k]; v.y = ys[k]; v.z = zs[k];
            v.w = __int_as_float((zi[k] & 255) | (lo << 8));
            g_atoms[a] = v;
        }
    } else {
        for (int a = base; a < N; a++) {
            while (lo + 1 < M && sp[lo + 1] <= a) lo++;
            float4 v;
            v.x = xyz[3 * a]; v.y = xyz[3 * a + 1]; v.z = xyz[3 * a + 2];
            v.w = __int_as_float((z[a] & 255) | (lo << 8));
            g_atoms[a] = v;
        }
    }
}

// ---------------- main edge kernel: 4 edges/thread, per-block consts ----------
__global__ void __launch_bounds__(256)
k_edges(const int4* __restrict__ nb4, const float4* __restrict__ off4,
        const int2* __restrict__ nb, const float* __restrict__ off,
        const float* __restrict__ d_inv,  const float* __restrict__ ze_inv,
        const float* __restrict__ c_inv,  const float* __restrict__ ex_inv,
        int E) {
    __shared__ float s_zpow[128];
    __shared__ float s_sp[10];        // c0..3, e0..3, d, ze (softplus'd)
    int t = threadIdx.x;

    // per-block constant computation (redundant but parallel across blocks)
    if (t < 4)       s_sp[t]     = log1pf(expf(__ldg(&c_inv[t])));
    else if (t < 8)  s_sp[t]     = log1pf(expf(__ldg(&ex_inv[t - 4])));
    else if (t == 8) s_sp[8]     = log1pf(expf(__ldg(&d_inv[0])));
    else if (t == 9) s_sp[9]     = log1pf(expf(__ldg(&ze_inv[0])));
    __syncthreads();
    if (t < 128) s_zpow[t] = (t == 0) ? 0.f : powf((float)t, s_sp[9]);
    __syncthreads();

    const float c0 = s_sp[0], c1 = s_sp[1], c2 = s_sp[2], c3 = s_sp[3];
    const float e0 = s_sp[4], e1 = s_sp[5], e2 = s_sp[6], e3 = s_sp[7];
    const float csi  = 1.f / (c0 + c1 + c2 + c3);
    const float dinv = 1.f / s_sp[8];
    const int slot = t & 31;

    auto body = [&](int i, int j, float ox, float oy, float oz) {
        if (j <= i) return;
        float4 ai = g_atoms[i];
        float4 aj = g_atoms[j];
        float dx = ai.x - aj.x - ox;
        float dy = ai.y - aj.y - oy;
        float dz = ai.z - aj.z - oz;
        float d2 = fmaf(dx, dx, fmaf(dy, dy, dz * dz)) + 3e-15f;
        if (d2 >= 25.f) return;
        float rinv = rsqrtf(d2);
        float r    = d2 * rinv;
        int wi = __float_as_int(ai.w);
        int wj = __float_as_int(aj.w);
        float zp = s_zpow[wi & 255] + s_zpow[wj & 255];
        float tt = -r * zp * dinv;
        float phi = fmaf(c0, __expf(e0 * tt),
                    fmaf(c1, __expf(e1 * tt),
                    fmaf(c2, __expf(e2 * tt),
                         c3 * __expf(e3 * tt))));
        float fcut = __expf(__fdividef(-d2, 25.f - d2));
        float zif = (float)(wi & 255);
        float zjf = (float)(wj & 255);
        float pair = KE_KCAL * zif * zjf * rinv * phi * csi * fcut;
        atomicAdd(&g_acc[((wi >> 8) << 5) + slot], pair);
    };

    int gt = blockIdx.x * blockDim.x + t;
    int G = E >> 2;            // groups of 4 edges
    if (gt < G) {
        int4 n01 = __ldcs(&nb4[2 * gt]);
        int4 n23 = __ldcs(&nb4[2 * gt + 1]);
        float4 o0 = __ldcs(&off4[3 * gt]);
        float4 o1 = __ldcs(&off4[3 * gt + 1]);
        float4 o2 = __ldcs(&off4[3 * gt + 2]);
        body(n01.x, n01.y, o0.x, o0.y, o0.z);
        body(n01.z, n01.w, o0.w, o1.x, o1.y);
        body(n23.x, n23.y, o1.z, o1.w, o2.x);
        body(n23.z, n23.w, o2.y, o2.z, o2.w);
    }
    if (gt == 0) {             // tail edges
        for (int e = G * 4; e < E; e++) {
            int2 p = nb[e];
            body(p.x, p.y, off[3 * e], off[3 * e + 1], off[3 * e + 2]);
        }
    }
}

// ---------------- final reduce: one warp per molecule ----------------
__global__ void __launch_bounds__(256)
k_reduce(float* __restrict__ out, int M) {
    int gt = blockIdx.x * blockDim.x + threadIdx.x;
    int m = gt >> 5, lane = gt & 31;
    if (m >= M) return;
    float v = g_acc[(m << 5) + lane];
    #pragma unroll
    for (int o = 16; o > 0; o >>= 1)
        v += __shfl_down_sync(0xffffffffu, v, o);
    if (lane == 0) out[m] = v;
}

// ---------------- launch ----------------
extern "C" void kernel_launch(void* const* d_in, const int* in_sizes, int n_in,
                              void* d_out, int out_size) {
    const float* xyz    = (const float*)d_in[0];
    const int*   z      = (const int*)  d_in[1];
    const int*   nbrs   = (const int*)  d_in[2];
    const int*   natoms = (const int*)  d_in[3];
    const float* off    = (const float*)d_in[4];
    const float* d_inv  = (const float*)d_in[5];
    const float* ze_inv = (const float*)d_in[6];
    const float* c_inv  = (const float*)d_in[7];
    const float* ex_inv = (const float*)d_in[8];

    int N = in_sizes[1];
    int E = in_sizes[2] / 2;
    int M = in_sizes[3];
    float* out = (float*)d_out;

    int atomThreads = (N + 3) / 4;
    k_atoms<<<(atomThreads + 255) / 256, 256>>>(xyz, z, natoms, N, M);
    int G = E / 4;
    k_edges<<<(G + 255) / 256, 256>>>((const int4*)nbrs, (const float4*)off,
                                      (const int2*)nbrs, off,
                                      d_inv, ze_inv, c_inv, ex_inv, E);
    k_reduce<<<(M * 32 + 255) / 256, 256>>>(out, M);
}

// round 5
// speedup vs baseline: 1.4359x; 1.0911x over previous
#include <cuda_runtime.h>
#include <math.h>

#define KE_KCAL 332.0636f

// ---------------- scratch (no allocations allowed) ----------------
__device__ float4 g_atoms[262144];    // packed per-atom: x,y,z, (z | mol<<8)
__device__ float  g_acc[1024 * 32];   // padded per-molecule accumulators
__device__ float  g_zpd[128];         // z^z_exp / d  (dinv folded in)
__device__ float  g_k[8];             // c0'..c3' (KE*csi folded), e0..e3

// ---------------- atom packing (1 atom/thread) + consts + acc zero ----------
__global__ void __launch_bounds__(256)
k_atoms(const float* __restrict__ xyz,
        const int*   __restrict__ z,
        const int*   __restrict__ na,
        const float* __restrict__ d_inv,  const float* __restrict__ ze_inv,
        const float* __restrict__ c_inv,  const float* __restrict__ ex_inv,
        int N, int M) {
    __shared__ int sp[1026];          // exclusive prefix; sp[M]=total, sentinel
    __shared__ int s_wsum[8];
    int t = threadIdx.x;
    int lane = t & 31, warp = t >> 5;

    // ---- warp-shuffle scan of num_atoms (4 elems/thread, 256 threads -> 1024) ----
    int v0 = (4 * t + 0 < M) ? __ldg(&na[4 * t + 0]) : 0;
    int v1 = (4 * t + 1 < M) ? __ldg(&na[4 * t + 1]) : 0;
    int v2 = (4 * t + 2 < M) ? __ldg(&na[4 * t + 2]) : 0;
    int v3 = (4 * t + 3 < M) ? __ldg(&na[4 * t + 3]) : 0;
    int mysum = v0 + v1 + v2 + v3;
    int sc = mysum;
    #pragma unroll
    for (int o = 1; o < 32; o <<= 1) {
        int x = __shfl_up_sync(0xffffffffu, sc, o);
        if (lane >= o) sc += x;
    }
    if (lane == 31) s_wsum[warp] = sc;
    __syncthreads();
    if (warp == 0 && lane < 8) {
        int ws = s_wsum[lane];
        #pragma unroll
        for (int o = 1; o < 8; o <<= 1) {
            int x = __shfl_up_sync(0xffu, ws, o);
            if (lane >= o) ws += x;
        }
        s_wsum[lane] = ws;
    }
    __syncthreads();
    int base_excl = sc - mysum + (warp > 0 ? s_wsum[warp - 1] : 0);
    sp[4 * t + 0] = base_excl;
    sp[4 * t + 1] = base_excl + v0;
    sp[4 * t + 2] = base_excl + v0 + v1;
    sp[4 * t + 3] = base_excl + v0 + v1 + v2;
    if (t == 0) { sp[1024] = 0x7fffffff; sp[1025] = 0x7fffffff; }
    __syncthreads();

    int gtid = blockIdx.x * blockDim.x + t;

    // block 0: compute softplus consts + zpow table once (edges kernel waits)
    if (blockIdx.x == 0) {
        if (t < 4)       g_k[t + 4] = log1pf(expf(__ldg(&ex_inv[t])));
        else if (t == 4) {
            float csum = 0.f, cc[4];
            #pragma unroll
            for (int k = 0; k < 4; k++) {
                cc[k] = log1pf(expf(__ldg(&c_inv[k])));
                csum += cc[k];
            }
            float s = KE_KCAL / csum;
            #pragma unroll
            for (int k = 0; k < 4; k++) g_k[k] = cc[k] * s;
        }
        if (t >= 32 && t < 160) {
            int zz = t - 32;
            float ze = log1pf(expf(__ldg(&ze_inv[0])));
            float dinv = 1.f / log1pf(expf(__ldg(&d_inv[0])));
            g_zpd[zz] = (zz == 0) ? 0.f : powf((float)zz, ze) * dinv;
        }
    }

    // zero accumulators (first 2048 threads, float4 stores)
    if (gtid < 2048) {
        float4 zv = make_float4(0.f, 0.f, 0.f, 0.f);
        #pragma unroll
        for (int k = 0; k < 4; k++)
            ((float4*)g_acc)[gtid + k * 2048] = zv;
    }

    int a = gtid;
    if (a >= N) return;

    // binary search: largest m with sp[m] <= a
    int lo = 0, hi = M;
    while (hi - lo > 1) {
        int mid = (lo + hi) >> 1;
        if (sp[mid] <= a) lo = mid; else hi = mid;
    }

    float4 v;
    v.x = xyz[3 * a];
    v.y = xyz[3 * a + 1];
    v.z = xyz[3 * a + 2];
    v.w = __int_as_float((z[a] & 255) | (lo << 8));
    g_atoms[a] = v;
}

// ---------------- main edge kernel: 4 edges/thread ----------------
__global__ void __launch_bounds__(256)
k_edges(const int4* __restrict__ nb4, const float4* __restrict__ off4,
        const int2* __restrict__ nb, const float* __restrict__ off, int E) {
    __shared__ float s_zpd[128];
    int t = threadIdx.x;
    if (t < 128) s_zpd[t] = g_zpd[t];
    __syncthreads();

    const float c0 = g_k[0], c1 = g_k[1], c2 = g_k[2], c3 = g_k[3];
    const float e0 = g_k[4], e1 = g_k[5], e2 = g_k[6], e3 = g_k[7];
    const int slot = t & 31;

    auto body = [&](int i, int j, float ox, float oy, float oz) {
        if (j <= i) return;
        float4 ai = g_atoms[i];
        float4 aj = g_atoms[j];
        float dx = ai.x - aj.x - ox;
        float dy = ai.y - aj.y - oy;
        float dz = ai.z - aj.z - oz;
        float d2 = fmaf(dx, dx, fmaf(dy, dy, dz * dz)) + 3e-15f;
        if (d2 >= 25.f) return;
        float rinv = rsqrtf(d2);
        float r    = d2 * rinv;
        int wi = __float_as_int(ai.w);
        int wj = __float_as_int(aj.w);
        float tt = -r * (s_zpd[wi & 255] + s_zpd[wj & 255]);
        float phi = fmaf(c0, __expf(e0 * tt),
                    fmaf(c1, __expf(e1 * tt),
                    fmaf(c2, __expf(e2 * tt),
                         c3 * __expf(e3 * tt))));
        float fcut = __expf(__fdividef(-d2, 25.f - d2));
        float zif = (float)(wi & 255);
        float zjf = (float)(wj & 255);
        float pair = zif * zjf * rinv * phi * fcut;
        atomicAdd(&g_acc[((wi >> 8) << 5) + slot], pair);
    };

    int gt = blockIdx.x * blockDim.x + t;
    int G = E >> 2;            // groups of 4 edges
    if (gt < G) {
        int4 n01 = nb4[2 * gt];
        int4 n23 = nb4[2 * gt + 1];
        float4 o0 = off4[3 * gt];
        float4 o1 = off4[3 * gt + 1];
        float4 o2 = off4[3 * gt + 2];
        body(n01.x, n01.y, o0.x, o0.y, o0.z);
        body(n01.z, n01.w, o0.w, o1.x, o1.y);
        body(n23.x, n23.y, o1.z, o1.w, o2.x);
        body(n23.z, n23.w, o2.y, o2.z, o2.w);
    }
    if (gt == 0) {             // tail edges
        for (int e = G * 4; e < E; e++) {
            int2 p = nb[e];
            body(p.x, p.y, off[3 * e], off[3 * e + 1], off[3 * e + 2]);
        }
    }
}

// ---------------- final reduce: one warp per molecule ----------------
__global__ void __launch_bounds__(256)
k_reduce(float* __restrict__ out, int M) {
    int gt = blockIdx.x * blockDim.x + threadIdx.x;
    int m = gt >> 5, lane = gt & 31;
    if (m >= M) return;
    float v = g_acc[(m << 5) + lane];
    #pragma unroll
    for (int o = 16; o > 0; o >>= 1)
        v += __shfl_down_sync(0xffffffffu, v, o);
    if (lane == 0) out[m] = v;
}

// ---------------- launch ----------------
extern "C" void kernel_launch(void* const* d_in, const int* in_sizes, int n_in,
                              void* d_out, int out_size) {
    const float* xyz    = (const float*)d_in[0];
    const int*   z      = (const int*)  d_in[1];
    const int*   nbrs   = (const int*)  d_in[2];
    const int*   natoms = (const int*)  d_in[3];
    const float* off    = (const float*)d_in[4];
    const float* d_inv  = (const float*)d_in[5];
    const float* ze_inv = (const float*)d_in[6];
    const float* c_inv  = (const float*)d_in[7];
    const float* ex_inv = (const float*)d_in[8];

    int N = in_sizes[1];
    int E = in_sizes[2] / 2;
    int M = in_sizes[3];
    float* out = (float*)d_out;

    k_atoms<<<(N + 255) / 256, 256>>>(xyz, z, natoms,
                                      d_inv, ze_inv, c_inv, ex_inv, N, M);
    int G = E / 4;
    k_edges<<<(G + 255) / 256, 256>>>((const int4*)nbrs, (const float4*)off,
                                      (const int2*)nbrs, off, E);
    k_reduce<<<(M * 32 + 255) / 256, 256>>>(out, M);
}